// round 16
// baseline (speedup 1.0000x reference)
#include <cuda_runtime.h>
#include <cuda_fp16.h>

#define NN 100000
#define NE 1600000
#define EPSV 1e-16f
#define NEG 0.2f

// Scratch (static __device__ — allocation-free)
__device__ float    g_rec1[NN * 8];  // per node: {as1[4], x0,x1,x2,0}
__device__ float    g_ad1[NN * 4];   // ad1 per node (4 heads)
__device__ float    g_acc1[NN * 16]; // layer1 rank-3 accumulators
__device__ __half   g_h2h[NN * 32];  // layer2 input features (fp16)
__device__ float    g_as2[NN];
__device__ float    g_ad2[NN];
__device__ float    g_acc2[NN * 32]; // layer2 weighted-sum accumulator (fp32)
__device__ float    g_den2[NN];      // layer2 softmax denominator
__device__ __half   g_uh[NN * 32];   // MLP u precompute (fp16)
__device__ __half   g_vh[NN * 32];   // MLP v precompute (fp16)
__device__ float    g_p[24];         // folded attn: p_src[4][3], p_dst[4][3]

__device__ __forceinline__ float lrelu(float x) { return x > 0.f ? x : NEG * x; }
__device__ __forceinline__ float eluf(float x)  { return x > 0.f ? x : (__expf(x) - 1.f); }

__device__ __forceinline__ void red4(float* p, float a, float b, float c, float d) {
    asm volatile("red.global.add.v4.f32 [%0], {%1,%2,%3,%4};"
                 :: "l"(p), "f"(a), "f"(b), "f"(c), "f"(d) : "memory");
}
__device__ __forceinline__ void red1(float* p, float v) {
    asm volatile("red.global.add.f32 [%0], %1;" :: "l"(p), "f"(v) : "memory");
}

// ---------------------------------------------------------------- fold attn vectors into W1 (tiny)
__global__ void k_prep(const float* __restrict__ w1, const float* __restrict__ as_,
                       const float* __restrict__ ad_) {
    int t = threadIdx.x;
    if (t >= 24) return;
    int sd = t / 12;
    int h  = (t % 12) / 3;
    int j  = t % 3;
    const float* a = sd ? ad_ : as_;
    float acc = 0.f;
    for (int c = 0; c < 32; c++)
        acc += a[h * 32 + c] * w1[(h * 32 + c) * 3 + j];
    g_p[sd * 12 + h * 3 + j] = acc;
}

// ---------------------------------------------------------------- node1: thread per node (+ zero accumulators)
__global__ void k_node1(const float* __restrict__ x) {
    __shared__ float sp[24];
    if (threadIdx.x < 24) sp[threadIdx.x] = g_p[threadIdx.x];
    __syncthreads();
    int n = blockIdx.x * blockDim.x + threadIdx.x;
    if (n >= NN) return;
    float x0 = __ldg(x + n * 3);
    float x1 = __ldg(x + n * 3 + 1);
    float x2 = __ldg(x + n * 3 + 2);
    float4 as, ad;
    as.x = x0 * sp[0]  + x1 * sp[1]  + x2 * sp[2];
    as.y = x0 * sp[3]  + x1 * sp[4]  + x2 * sp[5];
    as.z = x0 * sp[6]  + x1 * sp[7]  + x2 * sp[8];
    as.w = x0 * sp[9]  + x1 * sp[10] + x2 * sp[11];
    ad.x = x0 * sp[12] + x1 * sp[13] + x2 * sp[14];
    ad.y = x0 * sp[15] + x1 * sp[16] + x2 * sp[17];
    ad.z = x0 * sp[18] + x1 * sp[19] + x2 * sp[20];
    ad.w = x0 * sp[21] + x1 * sp[22] + x2 * sp[23];
    *(float4*)(g_rec1 + n * 8)     = as;
    *(float4*)(g_rec1 + n * 8 + 4) = make_float4(x0, x1, x2, 0.f);
    *(float4*)(g_ad1 + n * 4)      = ad;
    float4 z = make_float4(0.f, 0.f, 0.f, 0.f);
#pragma unroll
    for (int j = 0; j < 4; j++) *(float4*)(g_acc1 + n * 16 + j * 4) = z;
#pragma unroll
    for (int j = 0; j < 8; j++) *(float4*)(g_acc2 + n * 32 + j * 4) = z;
    g_den2[n] = 0.f;
}

// ---------------------------------------------------------------- layer1 edge accumulation (thread per edge, 2x unroll)
__global__ void k_l1e(const int* __restrict__ src, const int* __restrict__ dst) {
    int i = blockIdx.x * blockDim.x + threadIdx.x;
    int st = gridDim.x * blockDim.x;
    for (int e = i; e < NE; e += 2 * st) {
        int e1 = e + st;
        bool h1 = e1 < NE;
        int s0 = src[e], d0 = dst[e];
        int s1 = h1 ? src[e1] : s0;
        int d1 = h1 ? dst[e1] : d0;
        // batch all gathers
        float4 as0 = *(const float4*)(g_rec1 + s0 * 8);
        float4 xx0 = *(const float4*)(g_rec1 + s0 * 8 + 4);
        float4 ad0 = *(const float4*)(g_ad1 + d0 * 4);
        float4 as1 = *(const float4*)(g_rec1 + s1 * 8);
        float4 xx1 = *(const float4*)(g_rec1 + s1 * 8 + 4);
        float4 ad1 = *(const float4*)(g_ad1 + d1 * 4);
        {
            float w0 = __expf(lrelu(as0.x + ad0.x));
            float w1 = __expf(lrelu(as0.y + ad0.y));
            float w2 = __expf(lrelu(as0.z + ad0.z));
            float w3 = __expf(lrelu(as0.w + ad0.w));
            float* p = g_acc1 + d0 * 16;
            red4(p,      w0 * xx0.x, w0 * xx0.y, w0 * xx0.z, w0);
            red4(p + 4,  w1 * xx0.x, w1 * xx0.y, w1 * xx0.z, w1);
            red4(p + 8,  w2 * xx0.x, w2 * xx0.y, w2 * xx0.z, w2);
            red4(p + 12, w3 * xx0.x, w3 * xx0.y, w3 * xx0.z, w3);
        }
        if (h1) {
            float w0 = __expf(lrelu(as1.x + ad1.x));
            float w1 = __expf(lrelu(as1.y + ad1.y));
            float w2 = __expf(lrelu(as1.z + ad1.z));
            float w3 = __expf(lrelu(as1.w + ad1.w));
            float* p = g_acc1 + d1 * 16;
            red4(p,      w0 * xx1.x, w0 * xx1.y, w0 * xx1.z, w0);
            red4(p + 4,  w1 * xx1.x, w1 * xx1.y, w1 * xx1.z, w1);
            red4(p + 8,  w2 * xx1.x, w2 * xx1.y, w2 * xx1.z, w2);
            red4(p + 12, w3 * xx1.x, w3 * xx1.y, w3 * xx1.z, w3);
        }
    }
}

// ---------------------------------------------------------------- layer1 node finalize, tiled GEMM
#define TILE_N 64
#define NTILES ((NN + TILE_N - 1) / TILE_N)

__device__ __forceinline__ int vidx(int kq, int nl) {
    return kq * 64 + (nl ^ (((kq >> 3) & 3) << 1));
}

__global__ void k_l1n(const float* __restrict__ w1, const float* __restrict__ w2,
                      const float* __restrict__ b1,
                      const float* __restrict__ a2s, const float* __restrict__ a2d) {
    __shared__ float4 s_v4[32 * 64];
    __shared__ float4 s_w2[128 * 8];
    int tid = threadIdx.x;
    for (int i = tid; i < 1024; i += 256) {
        int k = i >> 3, cg = i & 7;
        float4 wv;
        wv.x = __ldg(w2 + (cg * 4 + 0) * 128 + k);
        wv.y = __ldg(w2 + (cg * 4 + 1) * 128 + k);
        wv.z = __ldg(w2 + (cg * 4 + 2) * 128 + k);
        wv.w = __ldg(w2 + (cg * 4 + 3) * 128 + k);
        s_w2[i] = wv;
    }
    int wrp  = tid >> 5;
    int lane = tid & 31;
    int cg   = lane & 7;
    int grp  = lane >> 3;
    int sub  = lane & 7;
    int kq = wrp * 4 + grp;
    int hd = kq >> 3;
    float w1r[4][3], b1r[4];
#pragma unroll
    for (int c = 0; c < 4; c++) {
        int k0 = kq * 4 + c;
        w1r[c][0] = __ldg(w1 + k0 * 3);
        w1r[c][1] = __ldg(w1 + k0 * 3 + 1);
        w1r[c][2] = __ldg(w1 + k0 * 3 + 2);
        b1r[c]    = __ldg(b1 + k0);
    }
    float4 a2sv = *(const float4*)(a2s + cg * 4);
    float4 a2dv = *(const float4*)(a2d + cg * 4);

    for (int tile = blockIdx.x; tile < NTILES; tile += gridDim.x) {
        int nbase = tile * TILE_N;
        __syncthreads();
#pragma unroll
        for (int it = 0; it < 8; it++) {
            int nl = sub + it * 8;
            int n = nbase + nl;
            if (n < NN) {
                float4 A = *(const float4*)(g_acc1 + n * 16 + hd * 4);
                float inv = 1.f / (A.w + EPSV);
                float4 vv;
                vv.x = eluf((w1r[0][0] * A.x + w1r[0][1] * A.y + w1r[0][2] * A.z) * inv + b1r[0]);
                vv.y = eluf((w1r[1][0] * A.x + w1r[1][1] * A.y + w1r[1][2] * A.z) * inv + b1r[1]);
                vv.z = eluf((w1r[2][0] * A.x + w1r[2][1] * A.y + w1r[2][2] * A.z) * inv + b1r[2]);
                vv.w = eluf((w1r[3][0] * A.x + w1r[3][1] * A.y + w1r[3][2] * A.z) * inv + b1r[3]);
                s_v4[vidx(kq, nl)] = vv;
            }
        }
        __syncthreads();
        int ln0 = wrp * 8 + grp * 2;
        int ln1 = ln0 + 1;
        float4 acc0 = make_float4(0.f, 0.f, 0.f, 0.f);
        float4 acc1 = make_float4(0.f, 0.f, 0.f, 0.f);
#pragma unroll
        for (int k2 = 0; k2 < 32; k2++) {
            float4 v0 = s_v4[vidx(k2, ln0)];
            float4 v1 = s_v4[vidx(k2, ln1)];
            float4 wq;
            wq = s_w2[(k2 * 4 + 0) * 8 + cg];
            acc0.x += v0.x * wq.x; acc0.y += v0.x * wq.y; acc0.z += v0.x * wq.z; acc0.w += v0.x * wq.w;
            acc1.x += v1.x * wq.x; acc1.y += v1.x * wq.y; acc1.z += v1.x * wq.z; acc1.w += v1.x * wq.w;
            wq = s_w2[(k2 * 4 + 1) * 8 + cg];
            acc0.x += v0.y * wq.x; acc0.y += v0.y * wq.y; acc0.z += v0.y * wq.z; acc0.w += v0.y * wq.w;
            acc1.x += v1.y * wq.x; acc1.y += v1.y * wq.y; acc1.z += v1.y * wq.z; acc1.w += v1.y * wq.w;
            wq = s_w2[(k2 * 4 + 2) * 8 + cg];
            acc0.x += v0.z * wq.x; acc0.y += v0.z * wq.y; acc0.z += v0.z * wq.z; acc0.w += v0.z * wq.w;
            acc1.x += v1.z * wq.x; acc1.y += v1.z * wq.y; acc1.z += v1.z * wq.z; acc1.w += v1.z * wq.w;
            wq = s_w2[(k2 * 4 + 3) * 8 + cg];
            acc0.x += v0.w * wq.x; acc0.y += v0.w * wq.y; acc0.z += v0.w * wq.z; acc0.w += v0.w * wq.w;
            acc1.x += v1.w * wq.x; acc1.y += v1.w * wq.y; acc1.z += v1.w * wq.z; acc1.w += v1.w * wq.w;
        }
        int n0 = nbase + ln0, n1 = nbase + ln1;
        float ts0 = acc0.x * a2sv.x + acc0.y * a2sv.y + acc0.z * a2sv.z + acc0.w * a2sv.w;
        float td0 = acc0.x * a2dv.x + acc0.y * a2dv.y + acc0.z * a2dv.z + acc0.w * a2dv.w;
        float ts1 = acc1.x * a2sv.x + acc1.y * a2sv.y + acc1.z * a2sv.z + acc1.w * a2sv.w;
        float td1 = acc1.x * a2dv.x + acc1.y * a2dv.y + acc1.z * a2dv.z + acc1.w * a2dv.w;
#pragma unroll
        for (int o = 4; o > 0; o >>= 1) {
            ts0 += __shfl_xor_sync(0xffffffffu, ts0, o);
            td0 += __shfl_xor_sync(0xffffffffu, td0, o);
            ts1 += __shfl_xor_sync(0xffffffffu, ts1, o);
            td1 += __shfl_xor_sync(0xffffffffu, td1, o);
        }
        if (n0 < NN) {
            __half2 p0 = __floats2half2_rn(acc0.x, acc0.y);
            __half2 p1 = __floats2half2_rn(acc0.z, acc0.w);
            uint2 stv = make_uint2(*(unsigned*)&p0, *(unsigned*)&p1);
            *(uint2*)(g_h2h + n0 * 32 + cg * 4) = stv;
            if (cg == 0) { g_as2[n0] = ts0; g_ad2[n0] = td0; }
        }
        if (n1 < NN) {
            __half2 p0 = __floats2half2_rn(acc1.x, acc1.y);
            __half2 p1 = __floats2half2_rn(acc1.z, acc1.w);
            uint2 stv = make_uint2(*(unsigned*)&p0, *(unsigned*)&p1);
            *(uint2*)(g_h2h + n1 * 32 + cg * 4) = stv;
            if (cg == 0) { g_as2[n1] = ts1; g_ad2[n1] = td1; }
        }
    }
}

// ---------------------------------------------------------------- layer2 edge accumulation: 8 edges/warp, 4 lanes/edge
__global__ void k_l2e(const int* __restrict__ src, const int* __restrict__ dst) {
    int tid = threadIdx.x;
    int lane = tid & 31;
    int eidx = lane >> 2;     // 0..7
    int part = lane & 3;      // 0..3, covers 8 halves each
    int warp = (blockIdx.x * blockDim.x + tid) >> 5;
    int nw = (gridDim.x * blockDim.x) >> 5;
    for (int base = warp * 8; base < NE; base += nw * 8) {
        int e = base + eidx;   // NE % 8 == 0 → always valid
        int s = src[e], d = dst[e];
        float w = __expf(lrelu(g_as2[s] + g_ad2[d]));
        uint4 hr = *(const uint4*)(g_h2h + s * 32 + part * 8);
        float2 h0 = __half22float2(*(const __half2*)&hr.x);
        float2 h1 = __half22float2(*(const __half2*)&hr.y);
        float2 h2 = __half22float2(*(const __half2*)&hr.z);
        float2 h3 = __half22float2(*(const __half2*)&hr.w);
        float* p = g_acc2 + d * 32 + part * 8;
        red4(p,     w * h0.x, w * h0.y, w * h1.x, w * h1.y);
        red4(p + 4, w * h2.x, w * h2.y, w * h3.x, w * h3.y);
        if (part == 0) red1(g_den2 + d, w);
    }
}

// ---------------------------------------------------------------- layer2 node finalize (warp per node), writes fp16 u,v
__global__ void k_l2n(const float* __restrict__ b2, const float* __restrict__ mw1,
                      const float* __restrict__ mb1) {
    __shared__ float s_wa[32 * 32];
    __shared__ float s_wb[32 * 32];
    int tid = threadIdx.x;
    for (int i = tid; i < 1024; i += blockDim.x) {
        int r = i >> 5, k = i & 31;
        s_wa[k * 32 + r] = mw1[r * 64 + k];
        s_wb[k * 32 + r] = mw1[r * 64 + 32 + k];
    }
    __syncthreads();
    int lane = tid & 31;
    int warp = (blockIdx.x * blockDim.x + tid) >> 5;
    int nw = (gridDim.x * blockDim.x) >> 5;
    for (int n = warp; n < NN; n += nw) {
        float o = g_acc2[n * 32 + lane] / (g_den2[n] + EPSV) + __ldg(b2 + lane);
        float u0 = 0.f, u1 = 0.f, v0 = 0.f, v1 = 0.f;
#pragma unroll
        for (int k = 0; k < 32; k += 2) {
            float bc0 = __shfl_sync(0xffffffffu, o, k);
            float bc1 = __shfl_sync(0xffffffffu, o, k + 1);
            u0 += s_wa[k * 32 + lane] * bc0;
            u1 += s_wa[(k + 1) * 32 + lane] * bc1;
            v0 += s_wb[k * 32 + lane] * bc0;
            v1 += s_wb[(k + 1) * 32 + lane] * bc1;
        }
        g_uh[n * 32 + lane] = __float2half(u0 + u1);
        g_vh[n * 32 + lane] = __float2half(v0 + v1 + __ldg(mb1 + lane));
    }
}

// ---------------------------------------------------------------- edge MLP: 8 edges/warp, 4 lanes/edge
__global__ void k_mlp(const float* __restrict__ mw2, const float* __restrict__ mb2,
                      float* __restrict__ out,
                      const int* __restrict__ src, const int* __restrict__ dst) {
    int tid = threadIdx.x;
    int lane = tid & 31;
    int eidx = lane >> 2;
    int part = lane & 3;
    int warp = (blockIdx.x * blockDim.x + tid) >> 5;
    int nw = (gridDim.x * blockDim.x) >> 5;
    float w2r[8];
#pragma unroll
    for (int i = 0; i < 8; i++) w2r[i] = __ldg(mw2 + part * 8 + i);
    float fb = __ldg(mb2);
    for (int base = warp * 8; base < NE; base += nw * 8) {
        int e = base + eidx;   // NE % 8 == 0
        int s = src[e], d = dst[e];
        uint4 ur = *(const uint4*)(g_uh + s * 32 + part * 8);
        uint4 vr = *(const uint4*)(g_vh + d * 32 + part * 8);
        float2 u0 = __half22float2(*(const __half2*)&ur.x);
        float2 u1 = __half22float2(*(const __half2*)&ur.y);
        float2 u2 = __half22float2(*(const __half2*)&ur.z);
        float2 u3 = __half22float2(*(const __half2*)&ur.w);
        float2 v0 = __half22float2(*(const __half2*)&vr.x);
        float2 v1 = __half22float2(*(const __half2*)&vr.y);
        float2 v2 = __half22float2(*(const __half2*)&vr.z);
        float2 v3 = __half22float2(*(const __half2*)&vr.w);
        float t = fmaxf(u0.x + v0.x, 0.f) * w2r[0]
                + fmaxf(u0.y + v0.y, 0.f) * w2r[1]
                + fmaxf(u1.x + v1.x, 0.f) * w2r[2]
                + fmaxf(u1.y + v1.y, 0.f) * w2r[3]
                + fmaxf(u2.x + v2.x, 0.f) * w2r[4]
                + fmaxf(u2.y + v2.y, 0.f) * w2r[5]
                + fmaxf(u3.x + v3.x, 0.f) * w2r[6]
                + fmaxf(u3.y + v3.y, 0.f) * w2r[7];
        t += __shfl_xor_sync(0xffffffffu, t, 2);
        t += __shfl_xor_sync(0xffffffffu, t, 1);
        if (part == 0) out[e] = fmaxf(t + fb, 0.f);
    }
}

extern "C" void kernel_launch(void* const* d_in, const int* in_sizes, int n_in,
                              void* d_out, int out_size) {
    const float* x   = (const float*)d_in[0];
    const int*   ei  = (const int*)d_in[1];
    const float* w1  = (const float*)d_in[2];
    const float* as1 = (const float*)d_in[3];
    const float* ad1 = (const float*)d_in[4];
    const float* b1  = (const float*)d_in[5];
    const float* w2  = (const float*)d_in[6];
    const float* as2 = (const float*)d_in[7];
    const float* ad2 = (const float*)d_in[8];
    const float* b2  = (const float*)d_in[9];
    const float* mw1 = (const float*)d_in[10];
    const float* mb1 = (const float*)d_in[11];
    const float* mw2 = (const float*)d_in[12];
    const float* mb2 = (const float*)d_in[13];
    const int* src = ei;
    const int* dst = ei + NE;
    float* out = (float*)d_out;

    k_prep <<<1, 32>>>(w1, as1, ad1);
    k_node1<<<(NN + 255) / 256, 256>>>(x);
    k_l1e  <<<2048, 256>>>(src, dst);
    k_l1n  <<<NTILES, 256>>>(w1, w2, b1, as2, ad2);
    k_l2e  <<<2048, 256>>>(src, dst);
    k_l2n  <<<512, 256>>>(b2, mw1, mb1);
    k_mlp  <<<2048, 256>>>(mw2, mb2, out, src, dst);
}

// round 17
// speedup vs baseline: 1.0602x; 1.0602x over previous
#include <cuda_runtime.h>
#include <cuda_fp16.h>

#define NN 100000
#define NE 1600000
#define EPSV 1e-16f
#define NEG 0.2f

// Scratch (static __device__ — allocation-free)
__device__ float    g_rx[NN * 4];    // padded x per node {x0,x1,x2,0}
__device__ float    g_acc1[NN * 16]; // layer1 rank-3 accumulators
__device__ float    g_h2[NN * 32];   // layer2 input features
__device__ float    g_as2[NN];
__device__ float    g_ad2[NN];
__device__ float    g_acc2[NN * 32]; // layer2 weighted-sum accumulator
__device__ float    g_den2[NN];      // layer2 softmax denominator
__device__ __half   g_uh[NN * 32];   // MLP u precompute (fp16)
__device__ __half   g_vh[NN * 32];   // MLP v precompute (fp16)
__device__ float    g_p[24];         // folded attn: p_src[4][3], p_dst[4][3]

__device__ __forceinline__ float lrelu(float x) { return x > 0.f ? x : NEG * x; }
__device__ __forceinline__ float eluf(float x)  { return x > 0.f ? x : (__expf(x) - 1.f); }

__device__ __forceinline__ void red4(float* p, float a, float b, float c, float d) {
    asm volatile("red.global.add.v4.f32 [%0], {%1,%2,%3,%4};"
                 :: "l"(p), "f"(a), "f"(b), "f"(c), "f"(d) : "memory");
}
__device__ __forceinline__ void red1(float* p, float v) {
    asm volatile("red.global.add.f32 [%0], %1;" :: "l"(p), "f"(v) : "memory");
}

// ---------------------------------------------------------------- fold attn vectors into W1 (tiny)
__global__ void k_prep(const float* __restrict__ w1, const float* __restrict__ as_,
                       const float* __restrict__ ad_) {
    int t = threadIdx.x;
    if (t >= 24) return;
    int sd = t / 12;
    int h  = (t % 12) / 3;
    int j  = t % 3;
    const float* a = sd ? ad_ : as_;
    float acc = 0.f;
    for (int c = 0; c < 32; c++)
        acc += a[h * 32 + c] * w1[(h * 32 + c) * 3 + j];
    g_p[sd * 12 + h * 3 + j] = acc;
}

// ---------------------------------------------------------------- node1: thread per node (pad x + zero accumulators)
__global__ void k_node1(const float* __restrict__ x) {
    int n = blockIdx.x * blockDim.x + threadIdx.x;
    if (n >= NN) return;
    float x0 = __ldg(x + n * 3);
    float x1 = __ldg(x + n * 3 + 1);
    float x2 = __ldg(x + n * 3 + 2);
    *(float4*)(g_rx + n * 4) = make_float4(x0, x1, x2, 0.f);
    float4 z = make_float4(0.f, 0.f, 0.f, 0.f);
#pragma unroll
    for (int j = 0; j < 4; j++) *(float4*)(g_acc1 + n * 16 + j * 4) = z;
#pragma unroll
    for (int j = 0; j < 8; j++) *(float4*)(g_acc2 + n * 32 + j * 4) = z;
    g_den2[n] = 0.f;
}

// ---------------------------------------------------------------- layer1 edge accumulation (thread per edge)
// gather only x[s], x[d]; reconstruct as/ad from register-resident P
__global__ void k_l1e(const int* __restrict__ src, const int* __restrict__ dst) {
    // P coefficients in registers (L1-hit loads, once per thread)
    float ps[12], pd[12];
#pragma unroll
    for (int j = 0; j < 12; j++) { ps[j] = g_p[j]; pd[j] = g_p[12 + j]; }
    int i = blockIdx.x * blockDim.x + threadIdx.x;
    int st = gridDim.x * blockDim.x;
    for (int e = i; e < NE; e += st) {
        int s = src[e], d = dst[e];
        float4 xs = *(const float4*)(g_rx + s * 4);
        float4 xd = *(const float4*)(g_rx + d * 4);
        float w0 = __expf(lrelu((xs.x * ps[0] + xs.y * ps[1]  + xs.z * ps[2])
                              + (xd.x * pd[0] + xd.y * pd[1]  + xd.z * pd[2])));
        float w1 = __expf(lrelu((xs.x * ps[3] + xs.y * ps[4]  + xs.z * ps[5])
                              + (xd.x * pd[3] + xd.y * pd[4]  + xd.z * pd[5])));
        float w2 = __expf(lrelu((xs.x * ps[6] + xs.y * ps[7]  + xs.z * ps[8])
                              + (xd.x * pd[6] + xd.y * pd[7]  + xd.z * pd[8])));
        float w3 = __expf(lrelu((xs.x * ps[9] + xs.y * ps[10] + xs.z * ps[11])
                              + (xd.x * pd[9] + xd.y * pd[10] + xd.z * pd[11])));
        float* p = g_acc1 + d * 16;
        red4(p,      w0 * xs.x, w0 * xs.y, w0 * xs.z, w0);
        red4(p + 4,  w1 * xs.x, w1 * xs.y, w1 * xs.z, w1);
        red4(p + 8,  w2 * xs.x, w2 * xs.y, w2 * xs.z, w2);
        red4(p + 12, w3 * xs.x, w3 * xs.y, w3 * xs.z, w3);
    }
}

// ---------------------------------------------------------------- layer1 node finalize, tiled GEMM
#define TILE_N 64
#define NTILES ((NN + TILE_N - 1) / TILE_N)

__device__ __forceinline__ int vidx(int kq, int nl) {
    return kq * 64 + (nl ^ (((kq >> 3) & 3) << 1));
}

__global__ void __launch_bounds__(256, 4)
k_l1n(const float* __restrict__ w1, const float* __restrict__ w2,
      const float* __restrict__ b1,
      const float* __restrict__ a2s, const float* __restrict__ a2d) {
    __shared__ float4 s_v4[32 * 64];
    __shared__ float4 s_w2[128 * 8];
    int tid = threadIdx.x;
    for (int i = tid; i < 1024; i += 256) {
        int k = i >> 3, cg = i & 7;
        float4 wv;
        wv.x = __ldg(w2 + (cg * 4 + 0) * 128 + k);
        wv.y = __ldg(w2 + (cg * 4 + 1) * 128 + k);
        wv.z = __ldg(w2 + (cg * 4 + 2) * 128 + k);
        wv.w = __ldg(w2 + (cg * 4 + 3) * 128 + k);
        s_w2[i] = wv;
    }
    int wrp  = tid >> 5;
    int lane = tid & 31;
    int cg   = lane & 7;
    int grp  = lane >> 3;
    int sub  = lane & 7;
    int kq = wrp * 4 + grp;
    int hd = kq >> 3;
    float w1r[4][3], b1r[4];
#pragma unroll
    for (int c = 0; c < 4; c++) {
        int k0 = kq * 4 + c;
        w1r[c][0] = __ldg(w1 + k0 * 3);
        w1r[c][1] = __ldg(w1 + k0 * 3 + 1);
        w1r[c][2] = __ldg(w1 + k0 * 3 + 2);
        b1r[c]    = __ldg(b1 + k0);
    }
    float4 a2sv = *(const float4*)(a2s + cg * 4);
    float4 a2dv = *(const float4*)(a2d + cg * 4);

    for (int tile = blockIdx.x; tile < NTILES; tile += gridDim.x) {
        int nbase = tile * TILE_N;
        __syncthreads();
#pragma unroll
        for (int it = 0; it < 8; it++) {
            int nl = sub + it * 8;
            int n = nbase + nl;
            if (n < NN) {
                float4 A = *(const float4*)(g_acc1 + n * 16 + hd * 4);
                float inv = 1.f / (A.w + EPSV);
                float4 vv;
                vv.x = eluf((w1r[0][0] * A.x + w1r[0][1] * A.y + w1r[0][2] * A.z) * inv + b1r[0]);
                vv.y = eluf((w1r[1][0] * A.x + w1r[1][1] * A.y + w1r[1][2] * A.z) * inv + b1r[1]);
                vv.z = eluf((w1r[2][0] * A.x + w1r[2][1] * A.y + w1r[2][2] * A.z) * inv + b1r[2]);
                vv.w = eluf((w1r[3][0] * A.x + w1r[3][1] * A.y + w1r[3][2] * A.z) * inv + b1r[3]);
                s_v4[vidx(kq, nl)] = vv;
            }
        }
        __syncthreads();
        int ln0 = wrp * 8 + grp * 2;
        int ln1 = ln0 + 1;
        float4 acc0 = make_float4(0.f, 0.f, 0.f, 0.f);
        float4 acc1 = make_float4(0.f, 0.f, 0.f, 0.f);
#pragma unroll
        for (int k2 = 0; k2 < 32; k2++) {
            float4 v0 = s_v4[vidx(k2, ln0)];
            float4 v1 = s_v4[vidx(k2, ln1)];
            float4 wq;
            wq = s_w2[(k2 * 4 + 0) * 8 + cg];
            acc0.x += v0.x * wq.x; acc0.y += v0.x * wq.y; acc0.z += v0.x * wq.z; acc0.w += v0.x * wq.w;
            acc1.x += v1.x * wq.x; acc1.y += v1.x * wq.y; acc1.z += v1.x * wq.z; acc1.w += v1.x * wq.w;
            wq = s_w2[(k2 * 4 + 1) * 8 + cg];
            acc0.x += v0.y * wq.x; acc0.y += v0.y * wq.y; acc0.z += v0.y * wq.z; acc0.w += v0.y * wq.w;
            acc1.x += v1.y * wq.x; acc1.y += v1.y * wq.y; acc1.z += v1.y * wq.z; acc1.w += v1.y * wq.w;
            wq = s_w2[(k2 * 4 + 2) * 8 + cg];
            acc0.x += v0.z * wq.x; acc0.y += v0.z * wq.y; acc0.z += v0.z * wq.z; acc0.w += v0.z * wq.w;
            acc1.x += v1.z * wq.x; acc1.y += v1.z * wq.y; acc1.z += v1.z * wq.z; acc1.w += v1.z * wq.w;
            wq = s_w2[(k2 * 4 + 3) * 8 + cg];
            acc0.x += v0.w * wq.x; acc0.y += v0.w * wq.y; acc0.z += v0.w * wq.z; acc0.w += v0.w * wq.w;
            acc1.x += v1.w * wq.x; acc1.y += v1.w * wq.y; acc1.z += v1.w * wq.z; acc1.w += v1.w * wq.w;
        }
        int n0 = nbase + ln0, n1 = nbase + ln1;
        float ts0 = acc0.x * a2sv.x + acc0.y * a2sv.y + acc0.z * a2sv.z + acc0.w * a2sv.w;
        float td0 = acc0.x * a2dv.x + acc0.y * a2dv.y + acc0.z * a2dv.z + acc0.w * a2dv.w;
        float ts1 = acc1.x * a2sv.x + acc1.y * a2sv.y + acc1.z * a2sv.z + acc1.w * a2sv.w;
        float td1 = acc1.x * a2dv.x + acc1.y * a2dv.y + acc1.z * a2dv.z + acc1.w * a2dv.w;
#pragma unroll
        for (int o = 4; o > 0; o >>= 1) {
            ts0 += __shfl_xor_sync(0xffffffffu, ts0, o);
            td0 += __shfl_xor_sync(0xffffffffu, td0, o);
            ts1 += __shfl_xor_sync(0xffffffffu, ts1, o);
            td1 += __shfl_xor_sync(0xffffffffu, td1, o);
        }
        if (n0 < NN) {
            *(float4*)(g_h2 + n0 * 32 + cg * 4) = acc0;
            if (cg == 0) { g_as2[n0] = ts0; g_ad2[n0] = td0; }
        }
        if (n1 < NN) {
            *(float4*)(g_h2 + n1 * 32 + cg * 4) = acc1;
            if (cg == 0) { g_as2[n1] = ts1; g_ad2[n1] = td1; }
        }
    }
}

// ---------------------------------------------------------------- layer2 edge accumulation (8 lanes per edge)
__global__ void k_l2e(const int* __restrict__ src, const int* __restrict__ dst) {
    int tid = threadIdx.x;
    int lane = tid & 31;
    int sub = lane & 7;
    int warp = (blockIdx.x * blockDim.x + tid) >> 5;
    int nw = (gridDim.x * blockDim.x) >> 5;
    for (int base = warp * 4; base < NE; base += nw * 4) {
        int e = base + (lane >> 3);   // NE % 4 == 0 → always valid
        int s = src[e], d = dst[e];
        float w = __expf(lrelu(g_as2[s] + g_ad2[d]));
        float4 h = *(const float4*)(g_h2 + s * 32 + sub * 4);
        red4(g_acc2 + d * 32 + sub * 4, w * h.x, w * h.y, w * h.z, w * h.w);
        if (sub == 0) red1(g_den2 + d, w);
    }
}

// ---------------------------------------------------------------- layer2 node finalize (warp per node), writes fp16 u,v
__global__ void k_l2n(const float* __restrict__ b2, const float* __restrict__ mw1,
                      const float* __restrict__ mb1) {
    __shared__ float s_wa[32 * 32];
    __shared__ float s_wb[32 * 32];
    int tid = threadIdx.x;
    for (int i = tid; i < 1024; i += blockDim.x) {
        int r = i >> 5, k = i & 31;
        s_wa[k * 32 + r] = mw1[r * 64 + k];
        s_wb[k * 32 + r] = mw1[r * 64 + 32 + k];
    }
    __syncthreads();
    int lane = tid & 31;
    int warp = (blockIdx.x * blockDim.x + tid) >> 5;
    int nw = (gridDim.x * blockDim.x) >> 5;
    for (int n = warp; n < NN; n += nw) {
        float o = g_acc2[n * 32 + lane] / (g_den2[n] + EPSV) + __ldg(b2 + lane);
        float u0 = 0.f, u1 = 0.f, v0 = 0.f, v1 = 0.f;
#pragma unroll
        for (int k = 0; k < 32; k += 2) {
            float bc0 = __shfl_sync(0xffffffffu, o, k);
            float bc1 = __shfl_sync(0xffffffffu, o, k + 1);
            u0 += s_wa[k * 32 + lane] * bc0;
            u1 += s_wa[(k + 1) * 32 + lane] * bc1;
            v0 += s_wb[k * 32 + lane] * bc0;
            v1 += s_wb[(k + 1) * 32 + lane] * bc1;
        }
        g_uh[n * 32 + lane] = __float2half(u0 + u1);
        g_vh[n * 32 + lane] = __float2half(v0 + v1 + __ldg(mb1 + lane));
    }
}

// ---------------------------------------------------------------- edge MLP: 8 lanes per edge, fp16 gathers
__global__ void k_mlp(const float* __restrict__ mw2, const float* __restrict__ mb2,
                      float* __restrict__ out,
                      const int* __restrict__ src, const int* __restrict__ dst) {
    int tid = threadIdx.x;
    int lane = tid & 31;
    int sub = lane & 7;
    int warp = (blockIdx.x * blockDim.x + tid) >> 5;
    int nw = (gridDim.x * blockDim.x) >> 5;
    float4 w2v = *(const float4*)(mw2 + sub * 4);
    float fb = __ldg(mb2);
    for (int base = warp * 4; base < NE; base += nw * 4) {
        int e = base + (lane >> 3);
        int s = src[e], d = dst[e];
        uint2 ur = *(const uint2*)(g_uh + s * 32 + sub * 4);
        uint2 vr = *(const uint2*)(g_vh + d * 32 + sub * 4);
        float2 ua = __half22float2(*(const __half2*)&ur.x);
        float2 ub = __half22float2(*(const __half2*)&ur.y);
        float2 va = __half22float2(*(const __half2*)&vr.x);
        float2 vb = __half22float2(*(const __half2*)&vr.y);
        float t = fmaxf(ua.x + va.x, 0.f) * w2v.x
                + fmaxf(ua.y + va.y, 0.f) * w2v.y
                + fmaxf(ub.x + vb.x, 0.f) * w2v.z
                + fmaxf(ub.y + vb.y, 0.f) * w2v.w;
        t += __shfl_xor_sync(0xffffffffu, t, 4);
        t += __shfl_xor_sync(0xffffffffu, t, 2);
        t += __shfl_xor_sync(0xffffffffu, t, 1);
        if (sub == 0) out[e] = fmaxf(t + fb, 0.f);
    }
}

extern "C" void kernel_launch(void* const* d_in, const int* in_sizes, int n_in,
                              void* d_out, int out_size) {
    const float* x   = (const float*)d_in[0];
    const int*   ei  = (const int*)d_in[1];
    const float* w1  = (const float*)d_in[2];
    const float* as1 = (const float*)d_in[3];
    const float* ad1 = (const float*)d_in[4];
    const float* b1  = (const float*)d_in[5];
    const float* w2  = (const float*)d_in[6];
    const float* as2 = (const float*)d_in[7];
    const float* ad2 = (const float*)d_in[8];
    const float* b2  = (const float*)d_in[9];
    const float* mw1 = (const float*)d_in[10];
    const float* mb1 = (const float*)d_in[11];
    const float* mw2 = (const float*)d_in[12];
    const float* mb2 = (const float*)d_in[13];
    const int* src = ei;
    const int* dst = ei + NE;
    float* out = (float*)d_out;

    k_prep <<<1, 32>>>(w1, as1, ad1);
    k_node1<<<(NN + 255) / 256, 256>>>(x);
    k_l1e  <<<2048, 256>>>(src, dst);
    k_l1n  <<<NTILES, 256>>>(w1, w2, b1, as2, ad2);
    k_l2e  <<<2048, 256>>>(src, dst);
    k_l2n  <<<512, 256>>>(b2, mw1, mb1);
    k_mlp  <<<2048, 256>>>(mw2, mb2, out, src, dst);
}